// round 9
// baseline (speedup 1.0000x reference)
#include <cuda_runtime.h>
#include <math.h>

#define BH 512
#define BW 512
#define BB 8
#define HW (BH*BW)
#define NTHR 256
#define CHUNK 4096                 // pixels per block per class plane
#define NBLK2 (BB*HW/CHUNK)        // 512 stream blocks

// ---- device scratch (static zero-init; kernels self-clean for graph replay) ----
__device__ double g_acc[8];                   // [cls*4 + {sumNo,cntNo,sumObj,cntObj}]
__device__ unsigned int g_ticket;
__device__ unsigned int g_mask[BB*HW/4];      // 1 byte/px: bit0=obj0,1=out0,2=obj1,3=out1

__device__ __forceinline__ float ex2f_(float x){ float y; asm("ex2.approx.f32 %0,%1;" : "=f"(y) : "f"(x)); return y; }
__device__ __forceinline__ float lg2f_(float x){ float y; asm("lg2.approx.f32 %0,%1;" : "=f"(y) : "f"(x)); return y; }
__device__ __forceinline__ float rcpf_(float x){ float y; asm("rcp.approx.f32 %0,%1;" : "=f"(y) : "f"(x)); return y; }

// ------------------------------------------------------------------
// Kernel A: one block per target; rasterize outer/inner bits into g_mask.
// ------------------------------------------------------------------
__global__ __launch_bounds__(NTHR)
void stamp_kernel(const float* __restrict__ tgt, int nT) {
    const int j = blockIdx.x;
    if (j >= nT) return;
    const float* t = tgt + j * 7;
    const int b   = (int)t[0];
    const int cls = (int)t[1];
    float cx = t[2] * 0.125f, cy = t[3] * 0.125f;
    float ww = t[4] * 0.125f, hh = t[5] * 0.125f;
    float c = __cosf(t[6]), s = __sinf(t[6]);
    float x =  cx * c + cy * s;
    float y = -cx * s + cy * c;
    const float X3 = x - hh * 0.5f, X4 = x + hh * 0.5f;
    const float Y3 = y - ww * 0.5f, Y4 = y + ww * 0.5f;
    const float X1 = X3 - 0.5f, X2 = X4 + 0.5f;
    const float Y1 = Y3 - 0.5f, Y2 = Y4 + 0.5f;

    // image-space AABB of the outer rotated rect: gx = c*vx - s*vy, gy = s*vx + c*vy
    float gxmin = 1e30f, gxmax = -1e30f, gymin = 1e30f, gymax = -1e30f;
    #pragma unroll
    for (int k = 0; k < 4; k++) {
        float vx = (k & 1) ? X2 : X1;
        float vy = (k & 2) ? Y2 : Y1;
        float gx = c * vx - s * vy;
        float gy = s * vx + c * vy;
        gxmin = fminf(gxmin, gx); gxmax = fmaxf(gxmax, gx);
        gymin = fminf(gymin, gy); gymax = fmaxf(gymax, gy);
    }
    int ix0 = max(0, (int)floorf(gxmin - 0.5f));
    int ix1 = min(BW - 1, (int)ceilf(gxmax - 0.5f) + 1);
    int iy0 = max(0, (int)floorf(gymin - 0.5f));
    int iy1 = min(BH - 1, (int)ceilf(gymax - 0.5f) + 1);
    int Wr = ix1 - ix0 + 1, Hr = iy1 - iy0 + 1;
    if (Wr <= 0 || Hr <= 0) return;

    const unsigned shbase = (unsigned)cls * 2u;
    for (int idx = threadIdx.x; idx < Wr * Hr; idx += NTHR) {
        int ix = ix0 + idx % Wr;
        int iy = iy0 + idx / Wr;
        float gx = ix + 0.5f, gy = iy + 0.5f;
        float vx = fmaf(c, gx, s * gy);
        float vy = fmaf(-s, gx, c * gy);
        bool outer = (vx >= X1) & (vx <= X2) & (vy >= Y1) & (vy <= Y2);
        if (outer) {
            bool inner = (vx >= X3) & (vx <= X4) & (vy >= Y3) & (vy <= Y4);
            unsigned p = (unsigned)b * HW + (unsigned)iy * BW + (unsigned)ix;
            unsigned bits = ((inner ? 1u : 0u) | 2u) << shbase;   // obj|out for this class
            atomicOr(&g_mask[p >> 2], bits << ((p & 3u) * 8u));
        }
    }
}

// ------------------------------------------------------------------
// Kernel B: pure stream. One block = 4096-px chunk of one image.
// 256 threads x 16 px. Reads flags from g_mask, clears them (replay-safe).
// ------------------------------------------------------------------
__global__ __launch_bounds__(NTHR)
void stream_kernel(const float* __restrict__ pred, float* __restrict__ out) {
    __shared__ float sred[8][6];
    const int tid = threadIdx.x;
    const int b   = blockIdx.x >> 6;
    const int q   = blockIdx.x & 63;
    const int base = q * CHUNK + tid * 16;

    const float* p0 = pred + (size_t)(2 * b) * HW + base;
    const float* p1 = p0 + HW;
    float4 f0[4], f1[4];
    #pragma unroll
    for (int g = 0; g < 4; g++) {
        f0[g] = *(const float4*)(p0 + g * 4);
        f1[g] = *(const float4*)(p1 + g * 4);
    }
    uint4* mp = (uint4*)((char*)g_mask + (size_t)b * HW + base);
    uint4 mq = *mp;
    if (mq.x | mq.y | mq.z | mq.w) *mp = make_uint4(0u, 0u, 0u, 0u);  // self-clean

    const float LOG2E = 1.4426950408889634f;
    const float LN2   = 0.6931471805599453f;
    float* hout = out + 1 + (size_t)b * HW + base;

    float a0 = 0.f, o0 = 0.f, a1 = 0.f, o1 = 0.f;
    unsigned nc = 0u, oc = 0u;   // 16-bit fields [cls0 | cls1<<16], per-lane <=16
    unsigned mws[4] = {mq.x, mq.y, mq.z, mq.w};

    #pragma unroll
    for (int g = 0; g < 4; g++) {
        const float4 F0 = f0[g], F1 = f1[g];
        const unsigned mw = mws[g];
        float xl0[4] = {F0.x * LOG2E, F0.y * LOG2E, F0.z * LOG2E, F0.w * LOG2E};
        float xl1[4] = {F1.x * LOG2E, F1.y * LOG2E, F1.z * LOG2E, F1.w * LOG2E};
        float t0[4], t1[4];
        #pragma unroll
        for (int k = 0; k < 4; k++) { t0[k] = ex2f_(xl0[k]); t1[k] = ex2f_(xl1[k]); }

        // heatmap: batched reciprocal (1 RCP per 4 px); scalar stores (out+1 misaligns v4)
        float tm[4], d[4];
        #pragma unroll
        for (int k = 0; k < 4; k++) { tm[k] = fmaxf(t0[k], t1[k]); d[k] = 1.0f + tm[k]; }
        float p01 = d[0] * d[1], p23 = d[2] * d[3];
        float R   = rcpf_(p01 * p23);
        float r01 = R * p23, r23 = R * p01;
        float* hp = hout + g * 4;
        hp[0] = tm[0] * (r01 * d[1]);
        hp[1] = tm[1] * (r01 * d[0]);
        hp[2] = tm[2] * (r23 * d[3]);
        hp[3] = tm[3] * (r23 * d[2]);

        if (mw == 0u) {
            // pure noobj group: 1 LG2 per class for 4 px
            float P0 = (1.0f + t0[0]) * (1.0f + t0[1]) * (1.0f + t0[2]) * (1.0f + t0[3]);
            float P1 = (1.0f + t1[0]) * (1.0f + t1[1]) * (1.0f + t1[2]) * (1.0f + t1[3]);
            a0 += lg2f_(P0);
            a1 += lg2f_(P1);
            nc += 4u | (4u << 16);
        } else {
            #pragma unroll
            for (int k = 0; k < 4; k++) {
                unsigned byte_ = (mw >> (8 * k)) & 0xFu;
                float L0 = lg2f_(1.0f + t0[k]);
                float L1 = lg2f_(1.0f + t1[k]);
                unsigned ob0 =  byte_ & 1u;
                unsigned no0 = (byte_ & 2u) ? 0u : 1u;
                unsigned ob1 = (byte_ >> 2) & 1u;
                unsigned no1 = (byte_ & 8u) ? 0u : 1u;
                if (no0) a0 += L0;
                if (ob0) o0 += L0 - xl0[k];
                if (no1) a1 += L1;
                if (ob1) o1 += L1 - xl1[k];
                nc += no0 | (no1 << 16);
                oc += ob0 | (ob1 << 16);
            }
        }
    }

    // ---- block reduction: floats via shuffle, counts via REDUX ----
    #pragma unroll
    for (int off = 16; off; off >>= 1) {
        a0 += __shfl_down_sync(0xffffffffu, a0, off);
        o0 += __shfl_down_sync(0xffffffffu, o0, off);
        a1 += __shfl_down_sync(0xffffffffu, a1, off);
        o1 += __shfl_down_sync(0xffffffffu, o1, off);
    }
    nc = __reduce_add_sync(0xffffffffu, nc);   // per-warp field <=512, fits 16b
    oc = __reduce_add_sync(0xffffffffu, oc);
    const int wid = tid >> 5;
    if ((tid & 31) == 0) {
        sred[wid][0] = a0; sred[wid][1] = o0;
        sred[wid][2] = a1; sred[wid][3] = o1;
        sred[wid][4] = __uint_as_float(nc);
        sred[wid][5] = __uint_as_float(oc);
    }
    __syncthreads();
    if (tid < 4) {
        float ssum = 0.f;
        #pragma unroll
        for (int wv = 0; wv < 8; wv++) ssum += sred[wv][tid];
        // 0->sumNo0(g_acc[0]) 1->sumOb0(g_acc[2]) 2->sumNo1(g_acc[4]) 3->sumOb1(g_acc[6])
        if (ssum != 0.f) atomicAdd(&g_acc[tid * 2], (double)(ssum * LN2));
    } else if (tid == 4) {
        unsigned cNo0 = 0, cNo1 = 0;
        #pragma unroll
        for (int wv = 0; wv < 8; wv++) {
            unsigned cw = __float_as_uint(sred[wv][4]);
            cNo0 += cw & 0xffffu; cNo1 += cw >> 16;
        }
        if (cNo0) atomicAdd(&g_acc[1], (double)cNo0);
        if (cNo1) atomicAdd(&g_acc[5], (double)cNo1);
    } else if (tid == 5) {
        unsigned cOb0 = 0, cOb1 = 0;
        #pragma unroll
        for (int wv = 0; wv < 8; wv++) {
            unsigned cw = __float_as_uint(sred[wv][5]);
            cOb0 += cw & 0xffffu; cOb1 += cw >> 16;
        }
        if (cOb0) atomicAdd(&g_acc[3], (double)cOb0);
        if (cOb1) atomicAdd(&g_acc[7], (double)cOb1);
    }
    if (tid < 6) __threadfence();
    __syncthreads();

    // ---- last-block election: finalize scalar loss, self-clean ----
    if (tid == 0) {
        unsigned int ticket = atomicAdd(&g_ticket, 1u);
        if (ticket == NBLK2 - 1) {
            __threadfence();
            double a[8];
            #pragma unroll
            for (int j = 0; j < 8; j++)
                a[j] = *((volatile double*)&g_acc[j]);
            double loss = 0.0;
            #pragma unroll
            for (int cls = 0; cls < 2; cls++) {
                double sNo = a[cls * 4 + 0], cNo = a[cls * 4 + 1];
                double sOb = a[cls * 4 + 2], cOb = a[cls * 4 + 3];
                if (cOb > 0.0)
                    loss += sOb / fmax(cOb, 1.0) + sNo / fmax(cNo, 1.0);
            }
            out[0] = (float)loss;
            #pragma unroll
            for (int j = 0; j < 8; j++) g_acc[j] = 0.0;
            g_ticket = 0u;
            __threadfence();
        }
    }
}

// ------------------------------------------------------------------
extern "C" void kernel_launch(void* const* d_in, const int* in_sizes, int n_in,
                              void* d_out, int out_size) {
    const float* pred = (const float*)d_in[0];
    const float* tgt  = (const float*)d_in[1];
    int nT = in_sizes[1] / 7;
    float* out = (float*)d_out;

    if (nT > 0) stamp_kernel<<<nT, NTHR>>>(tgt, nT);
    stream_kernel<<<NBLK2, NTHR>>>(pred, out);
}